// round 13
// baseline (speedup 1.0000x reference)
#include <cuda_runtime.h>
#include <cstddef>

// Problem constants (from reference setup_inputs)
#define B      64
#define S      2048
#define D      768
#define D4     (D / 4)          // 192 float4 per row
#define POOL   32
#define L      8
#define NT     10
#define TOPK   4
#define T_OUT  (L + TOPK * L + 1 + S)   // 2089
#define X_OFF  (L + TOPK * L + 1)       // 41

#define ROWS   64
#define CHUNKS (S / ROWS)       // 32

// Compact scratch: per-(b,pool,chunk) key-dot of the chunk column-sum.
// Every slot written exactly once per launch -> deterministic.
// Layout [b][pool][chunk] so the select kernel reads coalesced.
__device__ float g_kdot[(size_t)B * POOL * CHUNKS];
__device__ int   g_sel[(size_t)B * TOPK];

// -------------------------------------------------------------------------
// Kernel 1: copy x -> out[:, X_OFF:, :] (float4, coalesced, plain ld/st)
// + chunk column-sum + in-block GEMV against the 32 pool keys (L2-hot).
// Extra grid column (chunk == CHUNKS) writes g-prompt + cls rows.
// Grid (CHUNKS+1, B), block = 192 threads (6 warps).
// -------------------------------------------------------------------------
__global__ __launch_bounds__(D4) void copy_reduce_kernel(
    const float4* __restrict__ x, float4* __restrict__ out,
    const float4* __restrict__ g_prompts, const float4* __restrict__ cls_token,
    const float*  __restrict__ e_keys,    const int* __restrict__ task_id_p)
{
    const int chunk = blockIdx.x;
    const int b     = blockIdx.y;
    const int t     = threadIdx.x;          // 0..191
    const int lane  = t & 31;
    const int warp  = t >> 5;               // 0..5

    if (chunk == CHUNKS) {
        // selection-independent rows: g-prompt [0,8), cls row 40
        float4* obase = out + (size_t)b * T_OUT * D4;
        const int task = *task_id_p;
        const float4* gsrc = g_prompts + (size_t)task * L * D4;
#pragma unroll
        for (int i = 0; i < L; i++)
            obase[i * D4 + t] = gsrc[i * D4 + t];
        obase[(size_t)(L + TOPK * L) * D4 + t] = cls_token[t];
        return;
    }

    // ---------------- bulk copy + chunk column-sum ----------------
    const float4* __restrict__ xrow =
        x + ((size_t)b * S + (size_t)chunk * ROWS) * D4 + t;
    float4* __restrict__ orow =
        out + ((size_t)b * T_OUT + X_OFF + (size_t)chunk * ROWS) * D4 + t;

    float4 acc = make_float4(0.f, 0.f, 0.f, 0.f);

#pragma unroll 16
    for (int r = 0; r < ROWS; r++) {
        float4 v = xrow[(size_t)r * D4];
        orow[(size_t)r * D4] = v;
        acc.x += v.x; acc.y += v.y; acc.z += v.z; acc.w += v.w;
    }

    // ---------------- block GEMV: chunk-sum . keys ----------------
    __shared__ float sq[D];                  // 3 KB
    reinterpret_cast<float4*>(sq)[t] = acc;
    __syncthreads();

    // 6 warps cover 32 pools (warps 0,1 take 6 pools; others 5)
    for (int p = warp; p < POOL; p += 6) {
        const float* key = e_keys + (size_t)p * D;
        float dot = 0.f;
#pragma unroll
        for (int j = 0; j < D / 32; j++) {
            const int d = lane + j * 32;
            dot += sq[d] * key[d];
        }
#pragma unroll
        for (int off = 16; off > 0; off >>= 1)
            dot += __shfl_xor_sync(0xFFFFFFFFu, dot, off);
        if (lane == 0)
            g_kdot[((size_t)b * POOL + p) * CHUNKS + chunk] = dot;
    }
}

// -------------------------------------------------------------------------
// Kernel 2 (only dependent tail): per-batch selection + e-prompt writes.
// Grid = B, 256 threads (8 warps). Query-norm and /S are common positive
// scales per batch -> irrelevant to top-k ordering, so sim is just
// (sum_c kdot) * rsqrt(|key|^2 + eps).
// -------------------------------------------------------------------------
__global__ __launch_bounds__(256) void select_write_kernel(
    const float*  __restrict__ e_keys,
    const float4* __restrict__ e_prompts,
    float4*       __restrict__ out)
{
    const int b    = blockIdx.x;
    const int tid  = threadIdx.x;
    const int lane = tid & 31;
    const int warp = tid >> 5;               // 0..7

    __shared__ float sim[POOL];
    __shared__ int   sel[TOPK];

    // warp w handles pools {w, w+8, w+16, w+24}
#pragma unroll
    for (int pi = 0; pi < POOL / 8; pi++) {
        const int p = warp + pi * 8;

        // lane c holds chunk c's kdot: coalesced 32-float read
        float ds = g_kdot[((size_t)b * POOL + p) * CHUNKS + lane];

        const float* key = e_keys + (size_t)p * D;
        float ksq = 0.f;
#pragma unroll
        for (int j = 0; j < D / 32; j++) {
            const float k = key[lane + j * 32];
            ksq += k * k;
        }
#pragma unroll
        for (int off = 16; off > 0; off >>= 1) {
            ds  += __shfl_xor_sync(0xFFFFFFFFu, ds,  off);
            ksq += __shfl_xor_sync(0xFFFFFFFFu, ksq, off);
        }
        if (lane == 0)
            sim[p] = ds * rsqrtf(ksq + 1e-12f);
    }
    __syncthreads();

    // top-4, descending, lowest index on tie (matches jax.lax.top_k)
    if (tid == 0) {
        unsigned taken = 0u;
        for (int k = 0; k < TOPK; k++) {
            int   bi = 0;
            float bv = -3.4e38f;
            for (int p = 0; p < POOL; p++) {
                if ((taken >> p) & 1u) continue;
                if (sim[p] > bv) { bv = sim[p]; bi = p; }
            }
            sel[k] = bi;
            g_sel[b * TOPK + k] = bi;        // (debug/consistency; cheap)
            taken |= 1u << bi;
        }
    }
    __syncthreads();

    // write selected e-prompt rows [8, 40): 32 rows x 192 float4,
    // 24 float4 per thread, sources are L2-hot.
    float4* edst = out + ((size_t)b * T_OUT + L) * D4;
#pragma unroll
    for (int k = 0; k < TOPK; k++) {
        const float4* esrc = e_prompts + (size_t)sel[k] * L * D4;
        for (int i = tid; i < L * D4; i += 256)
            edst[k * L * D4 + i] = esrc[i];
    }
}

// -------------------------------------------------------------------------
// Launch: big copy kernel + one small dependent tail kernel.
// -------------------------------------------------------------------------
extern "C" void kernel_launch(void* const* d_in, const int* in_sizes, int n_in,
                              void* d_out, int out_size)
{
    const float* x         = (const float*)d_in[0];   // [B,S,D]
    const float* g_prompts = (const float*)d_in[1];   // [NT,L,D]
    const float* e_prompts = (const float*)d_in[2];   // [POOL,L,D]
    const float* e_keys    = (const float*)d_in[3];   // [POOL,D]
    const float* cls_token = (const float*)d_in[4];   // [1,1,D]
    const int*   task_id   = (const int*)d_in[5];     // scalar
    float*       out       = (float*)d_out;           // [B,T_OUT,D]

    dim3 grid1(CHUNKS + 1, B);
    copy_reduce_kernel<<<grid1, D4>>>(
        reinterpret_cast<const float4*>(x),
        reinterpret_cast<float4*>(out),
        reinterpret_cast<const float4*>(g_prompts),
        reinterpret_cast<const float4*>(cls_token),
        e_keys, task_id);

    select_write_kernel<<<B, 256>>>(
        e_keys,
        reinterpret_cast<const float4*>(e_prompts),
        reinterpret_cast<float4*>(out));
}

// round 14
// speedup vs baseline: 1.0142x; 1.0142x over previous
#include <cuda_runtime.h>
#include <cstddef>

// Problem constants (from reference setup_inputs)
#define B      64
#define S      2048
#define D      768
#define D4     (D / 4)          // 192 float4 per row
#define POOL   32
#define L      8
#define NT     10
#define TOPK   4
#define T_OUT  (L + TOPK * L + 1 + S)   // 2089
#define X_OFF  (L + TOPK * L + 1)       // 41

#define ROWS   64
#define CHUNKS (S / ROWS)       // 32

#define NGROUPS 4

// Scratch (every slot written exactly once per launch -> deterministic)
__device__ float g_partial[(size_t)B * CHUNKS * D];   // per-(b,chunk) column sums
__device__ float g_query[(size_t)B * D];              // reduced query per b
__device__ float g_ksq[POOL];                         // |key_p|^2 (batch-indep)
__device__ int   g_sel[(size_t)B * TOPK];             // selected pool indices

// -------------------------------------------------------------------------
// Key-norm precompute: batch-independent, runs hidden under the first copy.
// One block, 32 warps, warp p reduces |key_p|^2.
// -------------------------------------------------------------------------
__global__ __launch_bounds__(1024) void ksq_kernel(const float* __restrict__ e_keys)
{
    const int warp = threadIdx.x >> 5;     // pool index 0..31
    const int lane = threadIdx.x & 31;
    const float* key = e_keys + (size_t)warp * D;
    float s = 0.f;
#pragma unroll
    for (int j = 0; j < D / 32; j++) {
        const float k = key[lane + j * 32];
        s += k * k;
    }
#pragma unroll
    for (int off = 16; off > 0; off >>= 1)
        s += __shfl_xor_sync(0xFFFFFFFFu, s, off);
    if (lane == 0) g_ksq[warp] = s;
}

// -------------------------------------------------------------------------
// Copy kernel (R5 body, proven fastest): copy x rows + chunk column sums.
// Extra grid column writes the selection-independent rows (g-prompt + cls).
// Grid (CHUNKS+1, nb) for batches [b0, b0+nb). Block = 192 threads.
// -------------------------------------------------------------------------
__global__ __launch_bounds__(D4) void copy_reduce_kernel(
    const float4* __restrict__ x, float4* __restrict__ out,
    const float4* __restrict__ g_prompts, const float4* __restrict__ cls_token,
    const int* __restrict__ task_id_p, int b0)
{
    const int chunk = blockIdx.x;
    const int b     = b0 + blockIdx.y;
    const int t     = threadIdx.x;

    if (chunk == CHUNKS) {
        float4* obase = out + (size_t)b * T_OUT * D4;
        const int task = *task_id_p;
        const float4* gsrc = g_prompts + (size_t)task * L * D4;
#pragma unroll
        for (int i = 0; i < L; i++)
            obase[i * D4 + t] = gsrc[i * D4 + t];
        obase[(size_t)(L + TOPK * L) * D4 + t] = cls_token[t];
        return;
    }

    const float4* __restrict__ xrow =
        x + ((size_t)b * S + (size_t)chunk * ROWS) * D4 + t;
    float4* __restrict__ orow =
        out + ((size_t)b * T_OUT + X_OFF + (size_t)chunk * ROWS) * D4 + t;

    float4 acc = make_float4(0.f, 0.f, 0.f, 0.f);

#pragma unroll 16
    for (int r = 0; r < ROWS; r++) {
        float4 v = xrow[(size_t)r * D4];
        orow[(size_t)r * D4] = v;
        acc.x += v.x; acc.y += v.y; acc.z += v.z; acc.w += v.w;
    }

    float4* p = reinterpret_cast<float4*>(g_partial);
    p[((size_t)b * CHUNKS + chunk) * D4 + t] = acc;
}

// -------------------------------------------------------------------------
// Query reduce for one batch group. Grid (3, nb), 256 threads.
// -------------------------------------------------------------------------
__global__ __launch_bounds__(256) void query_reduce_kernel(int b0)
{
    const int d = blockIdx.x * 256 + threadIdx.x;   // 0..767
    const int b = b0 + blockIdx.y;
    const float* p = g_partial + (size_t)b * CHUNKS * D + d;
    float s = 0.f;
#pragma unroll
    for (int c = 0; c < CHUNKS; c++) s += p[(size_t)c * D];
    g_query[(size_t)b * D + d] = s;
}

// -------------------------------------------------------------------------
// Selection for one batch group. Grid = nb, 256 threads (8 warps).
// Query-norm & /S are common positive scales -> irrelevant to ordering;
// key-norm comes precomputed from g_ksq.
// -------------------------------------------------------------------------
__global__ __launch_bounds__(256) void select_kernel(
    const float* __restrict__ e_keys, int b0)
{
    const int b    = b0 + blockIdx.x;
    const int tid  = threadIdx.x;
    const int lane = tid & 31;
    const int warp = tid >> 5;               // 0..7

    __shared__ float q[D];
    __shared__ float sim[POOL];

#pragma unroll
    for (int j = 0; j < 3; j++)
        q[tid + j * 256] = g_query[(size_t)b * D + tid + j * 256];
    __syncthreads();

    // warp w handles pools {w, w+8, w+16, w+24}
#pragma unroll
    for (int pi = 0; pi < POOL / 8; pi++) {
        const int p = warp + pi * 8;
        const float* key = e_keys + (size_t)p * D;
        float dot = 0.f;
#pragma unroll
        for (int j = 0; j < D / 32; j++) {
            const int d = lane + j * 32;
            dot += q[d] * key[d];
        }
#pragma unroll
        for (int off = 16; off > 0; off >>= 1)
            dot += __shfl_xor_sync(0xFFFFFFFFu, dot, off);
        if (lane == 0)
            sim[p] = dot * rsqrtf(g_ksq[p] + 1e-12f);
    }
    __syncthreads();

    // top-4, descending, lowest index on tie (matches jax.lax.top_k)
    if (tid == 0) {
        unsigned taken = 0u;
        for (int k = 0; k < TOPK; k++) {
            int   bi = 0;
            float bv = -3.4e38f;
            for (int p = 0; p < POOL; p++) {
                if ((taken >> p) & 1u) continue;
                if (sim[p] > bv) { bv = sim[p]; bi = p; }
            }
            g_sel[b * TOPK + k] = bi;
            taken |= 1u << bi;
        }
    }
}

// -------------------------------------------------------------------------
// e-prompt writes for one batch group. Grid (TOPK*L, nb), 192 threads.
// One block per output row.
// -------------------------------------------------------------------------
__global__ __launch_bounds__(D4) void eprompt_write_kernel(
    const float4* __restrict__ e_prompts, float4* __restrict__ out, int b0)
{
    const int r = blockIdx.x;              // 0..31
    const int b = b0 + blockIdx.y;
    const int t = threadIdx.x;

    const int k   = r >> 3;
    const int lr  = r & 7;
    const int idx = g_sel[b * TOPK + k];

    const float4* src = e_prompts + ((size_t)idx * L + lr) * D4;
    float4* dst = out + ((size_t)b * T_OUT + L + r) * D4;
    dst[t] = src[t];
}

// -------------------------------------------------------------------------
// Launch: 4 batch-group copies on the main stream; each group's tail runs
// on a forked stream concurrently with the next group's copy. Only the
// last (4-batch) group's tail is exposed. Fork-join via events is the
// standard capture pattern; streams/events are created lazily on the first
// (non-captured) call. No device memory is ever allocated here.
// -------------------------------------------------------------------------
extern "C" void kernel_launch(void* const* d_in, const int* in_sizes, int n_in,
                              void* d_out, int out_size)
{
    const float* x         = (const float*)d_in[0];   // [B,S,D]
    const float* g_prompts = (const float*)d_in[1];   // [NT,L,D]
    const float* e_prompts = (const float*)d_in[2];   // [POOL,L,D]
    const float* e_keys    = (const float*)d_in[3];   // [POOL,D]
    const float* cls_token = (const float*)d_in[4];   // [1,1,D]
    const int*   task_id   = (const int*)d_in[5];     // scalar
    float*       out       = (float*)d_out;           // [B,T_OUT,D]

    static cudaStream_t s2 = nullptr;
    static cudaEvent_t  evCopy[NGROUPS];
    static cudaEvent_t  evJoin;
    static cudaEvent_t  evFork;
    if (s2 == nullptr) {
        cudaStreamCreateWithFlags(&s2, cudaStreamNonBlocking);
        for (int g = 0; g < NGROUPS; g++)
            cudaEventCreateWithFlags(&evCopy[g], cudaEventDisableTiming);
        cudaEventCreateWithFlags(&evJoin, cudaEventDisableTiming);
        cudaEventCreateWithFlags(&evFork, cudaEventDisableTiming);
    }

    static const int B0[NGROUPS] = {0, 24, 48, 60};
    static const int NB[NGROUPS] = {24, 24, 12, 4};

    // Fork side stream from the captured (null) stream, then precompute
    // key norms there (independent work, hidden under the first copy).
    cudaEventRecord(evFork, 0);
    cudaStreamWaitEvent(s2, evFork, 0);
    ksq_kernel<<<1, 1024, 0, s2>>>(e_keys);

    // Sequential batch-group copies on the main stream.
    for (int g = 0; g < NGROUPS; g++) {
        dim3 grid(CHUNKS + 1, NB[g]);
        copy_reduce_kernel<<<grid, D4>>>(
            reinterpret_cast<const float4*>(x),
            reinterpret_cast<float4*>(out),
            reinterpret_cast<const float4*>(g_prompts),
            reinterpret_cast<const float4*>(cls_token),
            task_id, B0[g]);
        cudaEventRecord(evCopy[g], 0);
    }

    // Per-group tails on the side stream, each gated on its group's copy.
    for (int g = 0; g < NGROUPS; g++) {
        cudaStreamWaitEvent(s2, evCopy[g], 0);

        dim3 gq(3, NB[g]);
        query_reduce_kernel<<<gq, 256, 0, s2>>>(B0[g]);

        select_kernel<<<NB[g], 256, 0, s2>>>(e_keys, B0[g]);

        dim3 ge(TOPK * L, NB[g]);
        eprompt_write_kernel<<<ge, D4, 0, s2>>>(
            reinterpret_cast<const float4*>(e_prompts),
            reinterpret_cast<float4*>(out), B0[g]);
    }

    // Join back into the captured stream.
    cudaEventRecord(evJoin, s2);
    cudaStreamWaitEvent(0, evJoin, 0);
}